// round 15
// baseline (speedup 1.0000x reference)
#include <cuda_runtime.h>
#include <cuda_fp16.h>

#define DIMV   512
#define NROWS  16384
#define KCODES 8192

#define BM 64
#define BN 128
#define BK 64
#define NCHUNK (DIMV / BK)        // 8
#define NCT   (KCODES / BN)       // 64 column tiles
#define CPR   (NCT * 2)           // 128 candidate slots per row
#define EPSF  3.0f
#define MAXCAND 32
#define STAGE_BYTES 24576         // A 8KB + B 16KB
#define HSPLIT 60                 // tiles [0,60) HMMA, [60,64) FFMA

// ---------------- device globals (no runtime allocation allowed) ----------
__device__ __align__(16) __half g_xh[(size_t)NROWS * DIMV];
__device__ __align__(16) __half g_eh[(size_t)KCODES * DIMV];
__device__ float g_esq[KCODES];
__device__ unsigned long long g_cand[(size_t)NROWS * CPR];

// ---------------- packing: monotonic (score, smaller-idx-wins) ------------
__device__ __forceinline__ unsigned long long pack_score(float s, int idx) {
    unsigned u = __float_as_uint(s);
    u = (u & 0x80000000u) ? ~u : (u | 0x80000000u);
    return ((unsigned long long)u << 32) | (unsigned)(KCODES - 1 - idx);
}
__device__ __forceinline__ float unpack_score(unsigned long long p) {
    unsigned u = (unsigned)(p >> 32);
    u = (u & 0x80000000u) ? (u ^ 0x80000000u) : ~u;
    return __uint_as_float(u);
}
__device__ __forceinline__ int unpack_idx(unsigned long long p) {
    return KCODES - 1 - (int)(unsigned)(p & 0xFFFFFFFFu);
}
__device__ __forceinline__ void merge2(unsigned long long& a, unsigned long long& b,
                                       unsigned long long p) {
    if (p > a) { b = a; a = p; } else if (p > b) { b = p; }
}
__device__ __forceinline__ unsigned smem_u32(const void* p) {
    unsigned a;
    asm("{ .reg .u64 t; cvta.to.shared.u64 t, %1; cvt.u32.u64 %0, t; }"
        : "=r"(a) : "l"(p));
    return a;
}

// ---------------- kernel 1: fp16 conversion + |e|^2 ------------------------
__global__ void vq_prep(const float* __restrict__ x, const float* __restrict__ embed) {
    int b = blockIdx.x, tid = threadIdx.x;   // NROWS blocks x 128 threads
    float4 v = ((const float4*)(x + (size_t)b * DIMV))[tid];
    __half2 p0 = __floats2half2_rn(v.x, v.y);
    __half2 p1 = __floats2half2_rn(v.z, v.w);
    uint2 pk = make_uint2(*(unsigned*)&p0, *(unsigned*)&p1);
    *(uint2*)(g_xh + (size_t)b * DIMV + tid * 4) = pk;

    if (b < KCODES) {
        float4 e = ((const float4*)(embed + (size_t)b * DIMV))[tid];
        __half2 q0 = __floats2half2_rn(e.x, e.y);
        __half2 q1 = __floats2half2_rn(e.z, e.w);
        uint2 qk = make_uint2(*(unsigned*)&q0, *(unsigned*)&q1);
        *(uint2*)(g_eh + (size_t)b * DIMV + tid * 4) = qk;

        float s = e.x * e.x + e.y * e.y + e.z * e.z + e.w * e.w;
        #pragma unroll
        for (int o = 16; o > 0; o >>= 1) s += __shfl_down_sync(0xffffffffu, s, o);
        __shared__ float red[4];
        if ((tid & 31) == 0) red[tid >> 5] = s;
        __syncthreads();
        if (tid == 0) g_esq[b] = red[0] + red[1] + red[2] + red[3];
    }
}

// ---------------- kernel 2: hybrid HMMA(fp16) / FFMA(fp32) GEMM ------------
// CTA 64x128, 128 threads. blockIdx.x < HSPLIT: fp16 HMMA path (round-12).
// blockIdx.x >= HSPLIT: fp32 FFMA path (exact scores) using the idle FMA pipe.
__global__ __launch_bounds__(128, 4)
void vq_gemm(const float* __restrict__ x, const float* __restrict__ embed) {
    extern __shared__ char smem[];                // 2 stages x (A 8KB + B 16KB)
    __shared__ float s_esq[BN];
    __shared__ unsigned long long s_top[BM * 2];  // per-row {top1, top2}

    const int tid = threadIdx.x, lane = tid & 31, wn = tid >> 5;  // 4 warps
    const int rowBase = blockIdx.y * BM;
    const int colBase = blockIdx.x * BN;
    const unsigned sb = smem_u32(smem);

    s_esq[tid] = g_esq[colBase + tid];

    if (blockIdx.x >= HSPLIT) {
        // ================= FFMA path (exact fp32 scores) ====================
        float* As = (float*)smem;                 // [16][64]
        float* Bs = (float*)(smem + 4096);        // [16][128]
        const int tx = tid & 15, ty = tid >> 4;   // 16 col-groups x 8 row-groups

        float acc[8][8];
        #pragma unroll
        for (int i = 0; i < 8; i++)
            #pragma unroll
            for (int j = 0; j < 8; j++) acc[i][j] = 0.f;

        #pragma unroll 1
        for (int d0 = 0; d0 < DIMV; d0 += 16) {
            __syncthreads();
            #pragma unroll
            for (int it = 0; it < 2; it++) {      // A: 64 x 16 fp32
                int u = tid + it * 128;
                int r = u >> 2, qc = u & 3;
                float4 v = *(const float4*)(x + (size_t)(rowBase + r) * DIMV + d0 + qc * 4);
                As[(qc * 4 + 0) * 64 + r] = v.x;
                As[(qc * 4 + 1) * 64 + r] = v.y;
                As[(qc * 4 + 2) * 64 + r] = v.z;
                As[(qc * 4 + 3) * 64 + r] = v.w;
            }
            #pragma unroll
            for (int it = 0; it < 4; it++) {      // B: 128 x 16 fp32
                int u = tid + it * 128;
                int r = u >> 2, qc = u & 3;
                float4 v = *(const float4*)(embed + (size_t)(colBase + r) * DIMV + d0 + qc * 4);
                Bs[(qc * 4 + 0) * 128 + r] = v.x;
                Bs[(qc * 4 + 1) * 128 + r] = v.y;
                Bs[(qc * 4 + 2) * 128 + r] = v.z;
                Bs[(qc * 4 + 3) * 128 + r] = v.w;
            }
            __syncthreads();
            #pragma unroll
            for (int k = 0; k < 16; k++) {
                float rm[8], rn[8];
                *(float4*)&rm[0] = *(const float4*)&As[k * 64 + ty * 8];
                *(float4*)&rm[4] = *(const float4*)&As[k * 64 + ty * 8 + 4];
                *(float4*)&rn[0] = *(const float4*)&Bs[k * 128 + tx * 8];
                *(float4*)&rn[4] = *(const float4*)&Bs[k * 128 + tx * 8 + 4];
                #pragma unroll
                for (int i = 0; i < 8; i++)
                    #pragma unroll
                    for (int j = 0; j < 8; j++)
                        acc[i][j] = fmaf(rm[i], rn[j], acc[i][j]);
            }
        }

        // epilogue: per-row top-2 over 128 cols; reduce across 16 col-threads
        #pragma unroll
        for (int i = 0; i < 8; i++) {
            unsigned long long a = 0, b = 0;
            #pragma unroll
            for (int j = 0; j < 8; j++) {
                int cl = tx * 8 + j;
                float s = 2.f * acc[i][j] - s_esq[cl];
                merge2(a, b, pack_score(s, colBase + cl));
            }
            #pragma unroll
            for (int off = 1; off <= 8; off <<= 1) {
                unsigned long long xa = __shfl_xor_sync(0xffffffffu, a, off);
                unsigned long long xb = __shfl_xor_sync(0xffffffffu, b, off);
                merge2(a, b, xa); merge2(a, b, xb);
            }
            if (tx == 0) {
                int rl = ty * 8 + i;
                s_top[rl * 2] = a;
                s_top[rl * 2 + 1] = b;
            }
        }
        __syncthreads();
        g_cand[(size_t)(rowBase + (tid >> 1)) * CPR + blockIdx.x * 2 + (tid & 1)] =
            s_top[tid];
        return;
    }

    // ================= HMMA path (round-12, unchanged) ======================
    unsigned acc[4][4][2];
    #pragma unroll
    for (int mt = 0; mt < 4; mt++)
        #pragma unroll
        for (int nt = 0; nt < 4; nt++) {
            acc[mt][nt][0] = 0u; acc[mt][nt][1] = 0u;
        }

    #define ISSUE_CHUNK(c) do {                                              \
        const unsigned _aB = sb + ((c) & 1) * STAGE_BYTES;                   \
        const unsigned _bB = _aB + 8192u;                                    \
        const __half* _xp = g_xh + (size_t)rowBase * DIMV + (c) * BK;        \
        const __half* _ep = g_eh + (size_t)colBase * DIMV + (c) * BK;        \
        _Pragma("unroll")                                                    \
        for (int _it = 0; _it < 4; _it++) {                                  \
            int _u = tid + _it * 128;                                        \
            int _r = _u >> 3, _c = _u & 7;                                   \
            unsigned _off = _r * 128 + (((_c ^ (_r & 7))) << 4);             \
            asm volatile("cp.async.cg.shared.global [%0], [%1], 16;"         \
                :: "r"(_aB + _off), "l"(_xp + (size_t)_r * DIMV + _c * 8));  \
        }                                                                    \
        _Pragma("unroll")                                                    \
        for (int _it = 0; _it < 8; _it++) {                                  \
            int _u = tid + _it * 128;                                        \
            int _r = _u >> 3, _c = _u & 7;                                   \
            unsigned _off = _r * 128 + (((_c ^ (_r & 7))) << 4);             \
            asm volatile("cp.async.cg.shared.global [%0], [%1], 16;"         \
                :: "r"(_bB + _off), "l"(_ep + (size_t)_r * DIMV + _c * 8));  \
        }                                                                    \
        asm volatile("cp.async.commit_group;");                              \
    } while (0)

    #define LOAD_FRAGS(ks, s) do {                                           \
        _Pragma("unroll")                                                    \
        for (int _mt = 0; _mt < 4; _mt++) {                                  \
            int rA = _mt * 16 + (lane & 15);                                 \
            int cA = (ks) * 2 + (lane >> 4);                                 \
            unsigned addr = aBase + rA * 128 + (((cA ^ (rA & 7))) << 4);     \
            asm volatile("ldmatrix.sync.aligned.m8n8.x4.shared.b16 "         \
                         "{%0,%1,%2,%3}, [%4];"                              \
                         : "=r"(af[s][_mt][0]), "=r"(af[s][_mt][1]),         \
                           "=r"(af[s][_mt][2]), "=r"(af[s][_mt][3])          \
                         : "r"(addr));                                       \
        }                                                                    \
        _Pragma("unroll")                                                    \
        for (int _nt = 0; _nt < 4; _nt++) {                                  \
            int rB = wn * 32 + _nt * 8 + (lane & 7);                         \
            int cB = (ks) * 2 + ((lane >> 3) & 1);                           \
            unsigned addr = bBase + rB * 128 + (((cB ^ (rB & 7))) << 4);     \
            asm volatile("ldmatrix.sync.aligned.m8n8.x2.shared.b16 "         \
                         "{%0,%1}, [%2];"                                    \
                         : "=r"(bf[s][_nt][0]), "=r"(bf[s][_nt][1])          \
                         : "r"(addr));                                       \
        }                                                                    \
    } while (0)

    ISSUE_CHUNK(0);

    #pragma unroll 1
    for (int c = 0; c < NCHUNK; c++) {
        if (c < NCHUNK - 1) {
            ISSUE_CHUNK(c + 1);
            asm volatile("cp.async.wait_group 1;");
        } else {
            asm volatile("cp.async.wait_group 0;");
        }
        __syncthreads();

        const unsigned aBase = sb + (c & 1) * STAGE_BYTES;
        const unsigned bBase = aBase + 8192u;

        unsigned af[2][4][4], bf[2][4][2];
        LOAD_FRAGS(0, 0);

        #pragma unroll
        for (int ks = 0; ks < 4; ks++) {
            const int cur = ks & 1, nxt = cur ^ 1;
            if (ks < 3) LOAD_FRAGS(ks + 1, nxt);
            #pragma unroll
            for (int mt = 0; mt < 4; mt++)
                #pragma unroll
                for (int nt = 0; nt < 4; nt++)
                    asm volatile(
                        "mma.sync.aligned.m16n8k16.row.col.f16.f16.f16.f16 "
                        "{%0,%1}, {%2,%3,%4,%5}, {%6,%7}, {%0,%1};"
                        : "+r"(acc[mt][nt][0]), "+r"(acc[mt][nt][1])
                        : "r"(af[cur][mt][0]), "r"(af[cur][mt][1]),
                          "r"(af[cur][mt][2]), "r"(af[cur][mt][3]),
                          "r"(bf[cur][nt][0]), "r"(bf[cur][nt][1]));
        }
        __syncthreads();
    }

    // epilogue: CTA-wide top-2 per (row, 128-col tile)
    s_top[tid] = 0ULL;
    __syncthreads();

    const int gq = lane >> 2;
    const int qt = lane & 3;
    float esqv[4][2];
    #pragma unroll
    for (int nt = 0; nt < 4; nt++) {
        int cl = wn * 32 + nt * 8 + qt * 2;
        esqv[nt][0] = s_esq[cl];
        esqv[nt][1] = s_esq[cl + 1];
    }

    #pragma unroll
    for (int mt = 0; mt < 4; mt++) {
        int rl0 = mt * 16 + gq;
        int rl1 = rl0 + 8;
        unsigned long long a0 = 0, b0 = 0, a1 = 0, b1 = 0;
        #pragma unroll
        for (int nt = 0; nt < 4; nt++) {
            int cg = colBase + wn * 32 + nt * 8 + qt * 2;
            float2 c01 = __half22float2(*(__half2*)&acc[mt][nt][0]);
            float2 c23 = __half22float2(*(__half2*)&acc[mt][nt][1]);
            merge2(a0, b0, pack_score(2.f * c01.x - esqv[nt][0], cg));
            merge2(a0, b0, pack_score(2.f * c01.y - esqv[nt][1], cg + 1));
            merge2(a1, b1, pack_score(2.f * c23.x - esqv[nt][0], cg));
            merge2(a1, b1, pack_score(2.f * c23.y - esqv[nt][1], cg + 1));
        }
        #pragma unroll
        for (int off = 1; off <= 2; off <<= 1) {
            unsigned long long xa0 = __shfl_xor_sync(0xffffffffu, a0, off);
            unsigned long long xb0 = __shfl_xor_sync(0xffffffffu, b0, off);
            unsigned long long xa1 = __shfl_xor_sync(0xffffffffu, a1, off);
            unsigned long long xb1 = __shfl_xor_sync(0xffffffffu, b1, off);
            merge2(a0, b0, xa0); merge2(a0, b0, xb0);
            merge2(a1, b1, xa1); merge2(a1, b1, xb1);
        }
        if (qt == 0) {
            unsigned long long old0 = atomicMax(&s_top[rl0 * 2], a0);
            unsigned long long l0 = min(old0, a0);
            atomicMax(&s_top[rl0 * 2 + 1], max(l0, b0));
            unsigned long long old1 = atomicMax(&s_top[rl1 * 2], a1);
            unsigned long long l1 = min(old1, a1);
            atomicMax(&s_top[rl1 * 2 + 1], max(l1, b1));
        }
    }
    __syncthreads();

    g_cand[(size_t)(rowBase + (tid >> 1)) * CPR + blockIdx.x * 2 + (tid & 1)] =
        s_top[tid];
}

// ---------------- kernel 3: warp-per-row exact fp32 rescore + gather -------
__global__ __launch_bounds__(256)
void vq_rescore(const float* __restrict__ x, const float* __restrict__ embed,
                float* __restrict__ out, int write_idx) {
    const int warp = threadIdx.x >> 5, lane = threadIdx.x & 31;
    const int row = blockIdx.x * 8 + warp;
    __shared__ int s_idx[8][MAXCAND];
    __shared__ int s_cnt[8];
    if (lane == 0) s_cnt[warp] = 0;
    __syncwarp();

    const unsigned long long* cd = g_cand + (size_t)row * CPR;
    unsigned long long q[4];
    unsigned long long m = 0;
    #pragma unroll
    for (int i = 0; i < 4; i++) {
        q[i] = cd[i * 32 + lane];
        m = max(m, q[i]);
    }
    #pragma unroll
    for (int o = 16; o > 0; o >>= 1)
        m = max(m, __shfl_xor_sync(0xffffffffu, m, o));
    const float thr = unpack_score(m) - EPSF;

    #pragma unroll
    for (int i = 0; i < 4; i++) {
        if (unpack_score(q[i]) >= thr) {
            int k = atomicAdd(&s_cnt[warp], 1);
            if (k < MAXCAND) s_idx[warp][k] = unpack_idx(q[i]);
        }
    }
    __syncwarp();
    const int cnt = min(s_cnt[warp], MAXCAND);

    float4 xv[4];
    #pragma unroll
    for (int j = 0; j < 4; j++)
        xv[j] = ((const float4*)(x + (size_t)row * DIMV))[j * 32 + lane];

    unsigned long long best = 0ULL;
    for (int c = 0; c < cnt; c++) {
        const int idx = s_idx[warp][c];
        const float4* ev = (const float4*)(embed + (size_t)idx * DIMV);
        float d = 0.f;
        #pragma unroll
        for (int j = 0; j < 4; j++) {
            float4 e = ev[j * 32 + lane];
            d += xv[j].x * e.x + xv[j].y * e.y + xv[j].z * e.z + xv[j].w * e.w;
        }
        #pragma unroll
        for (int o = 16; o > 0; o >>= 1)
            d += __shfl_xor_sync(0xffffffffu, d, o);
        unsigned long long p = pack_score(2.0f * d - g_esq[idx], idx);
        if (p > best) best = p;
    }

    const int widx = unpack_idx(best);
    const float4* ev = (const float4*)(embed + (size_t)widx * DIMV);
    float4* dst = (float4*)(out + (size_t)row * DIMV);
    #pragma unroll
    for (int j = 0; j < 4; j++)
        dst[j * 32 + lane] = ev[j * 32 + lane];
    if (write_idx && lane == 0)
        out[(size_t)NROWS * DIMV + row] = (float)widx;
}

// ---------------- launch ----------------------------------------------------
extern "C" void kernel_launch(void* const* d_in, const int* in_sizes, int n_in,
                              void* d_out, int out_size) {
    const float* x     = (const float*)d_in[0];
    const float* embed = (const float*)d_in[1];
    float* out = (float*)d_out;

    cudaFuncSetAttribute(vq_gemm, cudaFuncAttributeMaxDynamicSharedMemorySize,
                         2 * STAGE_BYTES);

    vq_prep<<<NROWS, 128>>>(x, embed);

    dim3 grid(NCT, NROWS / BM);   // 64 x 256
    vq_gemm<<<grid, 128, 2 * STAGE_BYTES>>>(x, embed);

    int write_idx = (out_size >= NROWS * DIMV + NROWS) ? 1 : 0;
    vq_rescore<<<NROWS / 8, 256>>>(x, embed, out, write_idx);
}

// round 16
// speedup vs baseline: 1.4669x; 1.4669x over previous
#include <cuda_runtime.h>
#include <cuda_fp16.h>

#define DIMV   512
#define NROWS  16384
#define KCODES 8192

#define BM 64
#define BN 128
#define BK 64
#define NCHUNK (DIMV / BK)        // 8
#define NCT   (KCODES / BN)       // 64 column tiles
#define NRT   (NROWS / BM)        // 256 row tiles
#define NTILES (NCT * NRT)        // 16384
#define CPR   (NCT * 2)           // 128 candidate slots per row
#define EPSF  3.0f
#define MAXCAND 32
#define STAGE_BYTES 24576         // A 8KB + B 16KB
#define GRID_PERSIST (148 * 4)

// ---------------- device globals (no runtime allocation allowed) ----------
__device__ __align__(16) __half g_xh[(size_t)NROWS * DIMV];
__device__ __align__(16) __half g_eh[(size_t)KCODES * DIMV];
__device__ float g_esq[KCODES];
__device__ unsigned long long g_cand[(size_t)NROWS * CPR];

// ---------------- packing: monotonic (score, smaller-idx-wins) ------------
__device__ __forceinline__ unsigned long long pack_score(float s, int idx) {
    unsigned u = __float_as_uint(s);
    u = (u & 0x80000000u) ? ~u : (u | 0x80000000u);
    return ((unsigned long long)u << 32) | (unsigned)(KCODES - 1 - idx);
}
__device__ __forceinline__ float unpack_score(unsigned long long p) {
    unsigned u = (unsigned)(p >> 32);
    u = (u & 0x80000000u) ? (u ^ 0x80000000u) : ~u;
    return __uint_as_float(u);
}
__device__ __forceinline__ int unpack_idx(unsigned long long p) {
    return KCODES - 1 - (int)(unsigned)(p & 0xFFFFFFFFu);
}
__device__ __forceinline__ void merge2(unsigned long long& a, unsigned long long& b,
                                       unsigned long long p) {
    if (p > a) { b = a; a = p; } else if (p > b) { b = p; }
}
__device__ __forceinline__ unsigned smem_u32(const void* p) {
    unsigned a;
    asm("{ .reg .u64 t; cvta.to.shared.u64 t, %1; cvt.u32.u64 %0, t; }"
        : "=r"(a) : "l"(p));
    return a;
}

// ---------------- kernel 1: fp16 conversion + |e|^2 ------------------------
__global__ void vq_prep(const float* __restrict__ x, const float* __restrict__ embed) {
    int b = blockIdx.x, tid = threadIdx.x;   // NROWS blocks x 128 threads
    float4 v = ((const float4*)(x + (size_t)b * DIMV))[tid];
    __half2 p0 = __floats2half2_rn(v.x, v.y);
    __half2 p1 = __floats2half2_rn(v.z, v.w);
    uint2 pk = make_uint2(*(unsigned*)&p0, *(unsigned*)&p1);
    *(uint2*)(g_xh + (size_t)b * DIMV + tid * 4) = pk;

    if (b < KCODES) {
        float4 e = ((const float4*)(embed + (size_t)b * DIMV))[tid];
        __half2 q0 = __floats2half2_rn(e.x, e.y);
        __half2 q1 = __floats2half2_rn(e.z, e.w);
        uint2 qk = make_uint2(*(unsigned*)&q0, *(unsigned*)&q1);
        *(uint2*)(g_eh + (size_t)b * DIMV + tid * 4) = qk;

        float s = e.x * e.x + e.y * e.y + e.z * e.z + e.w * e.w;
        #pragma unroll
        for (int o = 16; o > 0; o >>= 1) s += __shfl_down_sync(0xffffffffu, s, o);
        __shared__ float red[4];
        if ((tid & 31) == 0) red[tid >> 5] = s;
        __syncthreads();
        if (tid == 0) g_esq[b] = red[0] + red[1] + red[2] + red[3];
    }
}

// ---------------- kernel 2: persistent fp16 HMMA GEMM, CTA 64x128 ----------
// 592 resident CTAs loop over 16384 tiles; inner code identical to round 12.
__global__ __launch_bounds__(128, 4)
void vq_gemm() {
    extern __shared__ char smem[];                // 2 stages x (A 8KB + B 16KB)
    __shared__ float s_esq[BN];
    __shared__ unsigned long long s_top[BM * 2];  // per-row {top1, top2}

    const int tid = threadIdx.x, lane = tid & 31, wn = tid >> 5;  // 4 warps
    const unsigned sb = smem_u32(smem);

    #define ISSUE_CHUNK(c) do {                                              \
        const unsigned _aB = sb + ((c) & 1) * STAGE_BYTES;                   \
        const unsigned _bB = _aB + 8192u;                                    \
        const __half* _xp = g_xh + (size_t)rowBase * DIMV + (c) * BK;        \
        const __half* _ep = g_eh + (size_t)colBase * DIMV + (c) * BK;        \
        _Pragma("unroll")                                                    \
        for (int _it = 0; _it < 4; _it++) {                                  \
            int _u = tid + _it * 128;                                        \
            int _r = _u >> 3, _c = _u & 7;                                   \
            unsigned _off = _r * 128 + (((_c ^ (_r & 7))) << 4);             \
            asm volatile("cp.async.cg.shared.global [%0], [%1], 16;"         \
                :: "r"(_aB + _off), "l"(_xp + (size_t)_r * DIMV + _c * 8));  \
        }                                                                    \
        _Pragma("unroll")                                                    \
        for (int _it = 0; _it < 8; _it++) {                                  \
            int _u = tid + _it * 128;                                        \
            int _r = _u >> 3, _c = _u & 7;                                   \
            unsigned _off = _r * 128 + (((_c ^ (_r & 7))) << 4);             \
            asm volatile("cp.async.cg.shared.global [%0], [%1], 16;"         \
                :: "r"(_bB + _off), "l"(_ep + (size_t)_r * DIMV + _c * 8));  \
        }                                                                    \
        asm volatile("cp.async.commit_group;");                              \
    } while (0)

    #define LOAD_FRAGS(ks, s) do {                                           \
        _Pragma("unroll")                                                    \
        for (int _mt = 0; _mt < 4; _mt++) {                                  \
            int rA = _mt * 16 + (lane & 15);                                 \
            int cA = (ks) * 2 + (lane >> 4);                                 \
            unsigned addr = aBase + rA * 128 + (((cA ^ (rA & 7))) << 4);     \
            asm volatile("ldmatrix.sync.aligned.m8n8.x4.shared.b16 "         \
                         "{%0,%1,%2,%3}, [%4];"                              \
                         : "=r"(af[s][_mt][0]), "=r"(af[s][_mt][1]),         \
                           "=r"(af[s][_mt][2]), "=r"(af[s][_mt][3])          \
                         : "r"(addr));                                       \
        }                                                                    \
        _Pragma("unroll")                                                    \
        for (int _nt = 0; _nt < 4; _nt++) {                                  \
            int rB = wn * 32 + _nt * 8 + (lane & 7);                         \
            int cB = (ks) * 2 + ((lane >> 3) & 1);                           \
            unsigned addr = bBase + rB * 128 + (((cB ^ (rB & 7))) << 4);     \
            asm volatile("ldmatrix.sync.aligned.m8n8.x2.shared.b16 "         \
                         "{%0,%1}, [%2];"                                    \
                         : "=r"(bf[s][_nt][0]), "=r"(bf[s][_nt][1])          \
                         : "r"(addr));                                       \
        }                                                                    \
    } while (0)

    #pragma unroll 1
    for (int tile = blockIdx.x; tile < NTILES; tile += GRID_PERSIST) {
        const int ctile = tile % NCT;
        const int rowBase = (tile / NCT) * BM;
        const int colBase = ctile * BN;

        s_esq[tid] = g_esq[colBase + tid];

        unsigned acc[4][4][2];
        #pragma unroll
        for (int mt = 0; mt < 4; mt++)
            #pragma unroll
            for (int nt = 0; nt < 4; nt++) {
                acc[mt][nt][0] = 0u; acc[mt][nt][1] = 0u;
            }

        ISSUE_CHUNK(0);

        #pragma unroll 1
        for (int c = 0; c < NCHUNK; c++) {
            if (c < NCHUNK - 1) {
                ISSUE_CHUNK(c + 1);
                asm volatile("cp.async.wait_group 1;");
            } else {
                asm volatile("cp.async.wait_group 0;");
            }
            __syncthreads();

            const unsigned aBase = sb + (c & 1) * STAGE_BYTES;
            const unsigned bBase = aBase + 8192u;

            unsigned af[2][4][4], bf[2][4][2];
            LOAD_FRAGS(0, 0);

            #pragma unroll
            for (int ks = 0; ks < 4; ks++) {
                const int cur = ks & 1, nxt = cur ^ 1;
                if (ks < 3) LOAD_FRAGS(ks + 1, nxt);
                #pragma unroll
                for (int mt = 0; mt < 4; mt++)
                    #pragma unroll
                    for (int nt = 0; nt < 4; nt++)
                        asm volatile(
                            "mma.sync.aligned.m16n8k16.row.col.f16.f16.f16.f16 "
                            "{%0,%1}, {%2,%3,%4,%5}, {%6,%7}, {%0,%1};"
                            : "+r"(acc[mt][nt][0]), "+r"(acc[mt][nt][1])
                            : "r"(af[cur][mt][0]), "r"(af[cur][mt][1]),
                              "r"(af[cur][mt][2]), "r"(af[cur][mt][3]),
                              "r"(bf[cur][nt][0]), "r"(bf[cur][nt][1]));
            }
            __syncthreads();
        }

        // ---- epilogue: CTA-wide top-2 per (row, 128-col tile) --------------
        s_top[tid] = 0ULL;             // 128 entries = 64 rows x 2 slots
        __syncthreads();

        const int gq = lane >> 2;      // row group 0..7
        const int qt = lane & 3;       // col quad 0..3
        float esqv[4][2];
        #pragma unroll
        for (int nt = 0; nt < 4; nt++) {
            int cl = wn * 32 + nt * 8 + qt * 2;
            esqv[nt][0] = s_esq[cl];
            esqv[nt][1] = s_esq[cl + 1];
        }

        #pragma unroll
        for (int mt = 0; mt < 4; mt++) {
            int rl0 = mt * 16 + gq;    // local rows 0..63
            int rl1 = rl0 + 8;
            unsigned long long a0 = 0, b0 = 0, a1 = 0, b1 = 0;
            #pragma unroll
            for (int nt = 0; nt < 4; nt++) {
                int cg = colBase + wn * 32 + nt * 8 + qt * 2;
                float2 c01 = __half22float2(*(__half2*)&acc[mt][nt][0]);
                float2 c23 = __half22float2(*(__half2*)&acc[mt][nt][1]);
                merge2(a0, b0, pack_score(2.f * c01.x - esqv[nt][0], cg));
                merge2(a0, b0, pack_score(2.f * c01.y - esqv[nt][1], cg + 1));
                merge2(a1, b1, pack_score(2.f * c23.x - esqv[nt][0], cg));
                merge2(a1, b1, pack_score(2.f * c23.y - esqv[nt][1], cg + 1));
            }
            #pragma unroll
            for (int off = 1; off <= 2; off <<= 1) {
                unsigned long long xa0 = __shfl_xor_sync(0xffffffffu, a0, off);
                unsigned long long xb0 = __shfl_xor_sync(0xffffffffu, b0, off);
                unsigned long long xa1 = __shfl_xor_sync(0xffffffffu, a1, off);
                unsigned long long xb1 = __shfl_xor_sync(0xffffffffu, b1, off);
                merge2(a0, b0, xa0); merge2(a0, b0, xb0);
                merge2(a1, b1, xa1); merge2(a1, b1, xb1);
            }
            if (qt == 0) {
                unsigned long long old0 = atomicMax(&s_top[rl0 * 2], a0);
                unsigned long long l0 = min(old0, a0);
                atomicMax(&s_top[rl0 * 2 + 1], max(l0, b0));
                unsigned long long old1 = atomicMax(&s_top[rl1 * 2], a1);
                unsigned long long l1 = min(old1, a1);
                atomicMax(&s_top[rl1 * 2 + 1], max(l1, b1));
            }
        }
        __syncthreads();

        // flush: 2 slots per row -> g_cand[row][ctile*2 + s]
        g_cand[(size_t)(rowBase + (tid >> 1)) * CPR + ctile * 2 + (tid & 1)] =
            s_top[tid];
    }
}

// ---------------- kernel 3: warp-per-row exact fp32 rescore + gather -------
__global__ __launch_bounds__(256)
void vq_rescore(const float* __restrict__ x, const float* __restrict__ embed,
                float* __restrict__ out, int write_idx) {
    const int warp = threadIdx.x >> 5, lane = threadIdx.x & 31;
    const int row = blockIdx.x * 8 + warp;
    __shared__ int s_idx[8][MAXCAND];
    __shared__ int s_cnt[8];
    if (lane == 0) s_cnt[warp] = 0;
    __syncwarp();

    const unsigned long long* cd = g_cand + (size_t)row * CPR;
    unsigned long long q[4];
    unsigned long long m = 0;
    #pragma unroll
    for (int i = 0; i < 4; i++) {
        q[i] = cd[i * 32 + lane];
        m = max(m, q[i]);
    }
    #pragma unroll
    for (int o = 16; o > 0; o >>= 1)
        m = max(m, __shfl_xor_sync(0xffffffffu, m, o));
    const float thr = unpack_score(m) - EPSF;

    #pragma unroll
    for (int i = 0; i < 4; i++) {
        if (unpack_score(q[i]) >= thr) {
            int k = atomicAdd(&s_cnt[warp], 1);
            if (k < MAXCAND) s_idx[warp][k] = unpack_idx(q[i]);
        }
    }
    __syncwarp();
    const int cnt = min(s_cnt[warp], MAXCAND);

    float4 xv[4];
    #pragma unroll
    for (int j = 0; j < 4; j++)
        xv[j] = ((const float4*)(x + (size_t)row * DIMV))[j * 32 + lane];

    unsigned long long best = 0ULL;
    for (int c = 0; c < cnt; c++) {
        const int idx = s_idx[warp][c];
        const float4* ev = (const float4*)(embed + (size_t)idx * DIMV);
        float d = 0.f;
        #pragma unroll
        for (int j = 0; j < 4; j++) {
            float4 e = ev[j * 32 + lane];
            d += xv[j].x * e.x + xv[j].y * e.y + xv[j].z * e.z + xv[j].w * e.w;
        }
        #pragma unroll
        for (int o = 16; o > 0; o >>= 1)
            d += __shfl_xor_sync(0xffffffffu, d, o);
        unsigned long long p = pack_score(2.0f * d - g_esq[idx], idx);
        if (p > best) best = p;
    }

    const int widx = unpack_idx(best);
    const float4* ev = (const float4*)(embed + (size_t)widx * DIMV);
    float4* dst = (float4*)(out + (size_t)row * DIMV);
    #pragma unroll
    for (int j = 0; j < 4; j++)
        dst[j * 32 + lane] = ev[j * 32 + lane];
    if (write_idx && lane == 0)
        out[(size_t)NROWS * DIMV + row] = (float)widx;
}

// ---------------- launch ----------------------------------------------------
extern "C" void kernel_launch(void* const* d_in, const int* in_sizes, int n_in,
                              void* d_out, int out_size) {
    const float* x     = (const float*)d_in[0];
    const float* embed = (const float*)d_in[1];
    float* out = (float*)d_out;

    cudaFuncSetAttribute(vq_gemm, cudaFuncAttributeMaxDynamicSharedMemorySize,
                         2 * STAGE_BYTES);

    vq_prep<<<NROWS, 128>>>(x, embed);

    vq_gemm<<<GRID_PERSIST, 128, 2 * STAGE_BYTES>>>();

    int write_idx = (out_size >= NROWS * DIMV + NROWS) ? 1 : 0;
    vq_rescore<<<NROWS / 8, 256>>>(x, embed, out, write_idx);
}

// round 17
// speedup vs baseline: 1.6897x; 1.1518x over previous
#include <cuda_runtime.h>
#include <cuda_fp16.h>

#define DIMV   512
#define NROWS  16384
#define KCODES 8192

#define BM 64
#define BN 128
#define BK 64
#define NCHUNK (DIMV / BK)        // 8
#define NCT   (KCODES / BN)       // 64 column tiles
#define CPR   (NCT * 2)           // 128 candidate slots per row
#define EPSF  3.0f
#define MAXCAND 32
#define STAGE_BYTES 24576         // A 8KB + B 16KB

// ---------------- device globals (no runtime allocation allowed) ----------
__device__ __align__(16) __half g_xh[(size_t)NROWS * DIMV];
__device__ __align__(16) __half g_eh[(size_t)KCODES * DIMV];
__device__ float g_esq[KCODES];
__device__ unsigned long long g_cand[(size_t)NROWS * CPR];

// ---------------- packing: monotonic (score, smaller-idx-wins) ------------
__device__ __forceinline__ unsigned long long pack_score(float s, int idx) {
    unsigned u = __float_as_uint(s);
    u = (u & 0x80000000u) ? ~u : (u | 0x80000000u);
    return ((unsigned long long)u << 32) | (unsigned)(KCODES - 1 - idx);
}
__device__ __forceinline__ float unpack_score(unsigned long long p) {
    unsigned u = (unsigned)(p >> 32);
    u = (u & 0x80000000u) ? (u ^ 0x80000000u) : ~u;
    return __uint_as_float(u);
}
__device__ __forceinline__ int unpack_idx(unsigned long long p) {
    return KCODES - 1 - (int)(unsigned)(p & 0xFFFFFFFFu);
}
__device__ __forceinline__ void merge2(unsigned long long& a, unsigned long long& b,
                                       unsigned long long p) {
    if (p > a) { b = a; a = p; } else if (p > b) { b = p; }
}
__device__ __forceinline__ unsigned smem_u32(const void* p) {
    unsigned a;
    asm("{ .reg .u64 t; cvta.to.shared.u64 t, %1; cvt.u32.u64 %0, t; }"
        : "=r"(a) : "l"(p));
    return a;
}

// ---------------- kernel 1: fp16 conversion + |e|^2 ------------------------
__global__ void vq_prep(const float* __restrict__ x, const float* __restrict__ embed) {
    int b = blockIdx.x, tid = threadIdx.x;   // NROWS blocks x 128 threads
    float4 v = ((const float4*)(x + (size_t)b * DIMV))[tid];
    __half2 p0 = __floats2half2_rn(v.x, v.y);
    __half2 p1 = __floats2half2_rn(v.z, v.w);
    uint2 pk = make_uint2(*(unsigned*)&p0, *(unsigned*)&p1);
    *(uint2*)(g_xh + (size_t)b * DIMV + tid * 4) = pk;

    if (b < KCODES) {
        float4 e = ((const float4*)(embed + (size_t)b * DIMV))[tid];
        __half2 q0 = __floats2half2_rn(e.x, e.y);
        __half2 q1 = __floats2half2_rn(e.z, e.w);
        uint2 qk = make_uint2(*(unsigned*)&q0, *(unsigned*)&q1);
        *(uint2*)(g_eh + (size_t)b * DIMV + tid * 4) = qk;

        float s = e.x * e.x + e.y * e.y + e.z * e.z + e.w * e.w;
        #pragma unroll
        for (int o = 16; o > 0; o >>= 1) s += __shfl_down_sync(0xffffffffu, s, o);
        __shared__ float red[4];
        if ((tid & 31) == 0) red[tid >> 5] = s;
        __syncthreads();
        if (tid == 0) g_esq[b] = red[0] + red[1] + red[2] + red[3];
    }
}

// ---------------- kernel 2: fp16 HMMA GEMM (f16 accum), CTA 64x128 ---------
// 4 warps (1x4 grid), warp tile 64x32, 4 CTAs/SM, 2-stage cp.async,
// ks-level fragment double-buffering.
__global__ __launch_bounds__(128, 4)
void vq_gemm() {
    extern __shared__ char smem[];                // 2 stages x (A 8KB + B 16KB)
    __shared__ float s_esq[BN];
    __shared__ unsigned long long s_top[BM * 2];  // per-row {top1, top2}

    const int tid = threadIdx.x, lane = tid & 31, wn = tid >> 5;  // 4 warps
    const int rowBase = blockIdx.y * BM;
    const int colBase = blockIdx.x * BN;
    const unsigned sb = smem_u32(smem);

    s_esq[tid] = g_esq[colBase + tid];

    // fp16 accumulators: 2 u32 (= 4 half) per 16x8 tile
    unsigned acc[4][4][2];
    #pragma unroll
    for (int mt = 0; mt < 4; mt++)
        #pragma unroll
        for (int nt = 0; nt < 4; nt++) {
            acc[mt][nt][0] = 0u; acc[mt][nt][1] = 0u;
        }

    // stage loader: A 64x128B (4 iters), B 128x128B (8 iters), XOR-swizzled
    #define ISSUE_CHUNK(c) do {                                              \
        const unsigned _aB = sb + ((c) & 1) * STAGE_BYTES;                   \
        const unsigned _bB = _aB + 8192u;                                    \
        const __half* _xp = g_xh + (size_t)rowBase * DIMV + (c) * BK;        \
        const __half* _ep = g_eh + (size_t)colBase * DIMV + (c) * BK;        \
        _Pragma("unroll")                                                    \
        for (int _it = 0; _it < 4; _it++) {                                  \
            int _u = tid + _it * 128;                                        \
            int _r = _u >> 3, _c = _u & 7;                                   \
            unsigned _off = _r * 128 + (((_c ^ (_r & 7))) << 4);             \
            asm volatile("cp.async.cg.shared.global [%0], [%1], 16;"         \
                :: "r"(_aB + _off), "l"(_xp + (size_t)_r * DIMV + _c * 8));  \
        }                                                                    \
        _Pragma("unroll")                                                    \
        for (int _it = 0; _it < 8; _it++) {                                  \
            int _u = tid + _it * 128;                                        \
            int _r = _u >> 3, _c = _u & 7;                                   \
            unsigned _off = _r * 128 + (((_c ^ (_r & 7))) << 4);             \
            asm volatile("cp.async.cg.shared.global [%0], [%1], 16;"         \
                :: "r"(_bB + _off), "l"(_ep + (size_t)_r * DIMV + _c * 8));  \
        }                                                                    \
        asm volatile("cp.async.commit_group;");                              \
    } while (0)

    #define LOAD_FRAGS(ks, s) do {                                           \
        _Pragma("unroll")                                                    \
        for (int _mt = 0; _mt < 4; _mt++) {                                  \
            int rA = _mt * 16 + (lane & 15);                                 \
            int cA = (ks) * 2 + (lane >> 4);                                 \
            unsigned addr = aBase + rA * 128 + (((cA ^ (rA & 7))) << 4);     \
            asm volatile("ldmatrix.sync.aligned.m8n8.x4.shared.b16 "         \
                         "{%0,%1,%2,%3}, [%4];"                              \
                         : "=r"(af[s][_mt][0]), "=r"(af[s][_mt][1]),         \
                           "=r"(af[s][_mt][2]), "=r"(af[s][_mt][3])          \
                         : "r"(addr));                                       \
        }                                                                    \
        _Pragma("unroll")                                                    \
        for (int _nt = 0; _nt < 4; _nt++) {                                  \
            int rB = wn * 32 + _nt * 8 + (lane & 7);                         \
            int cB = (ks) * 2 + ((lane >> 3) & 1);                           \
            unsigned addr = bBase + rB * 128 + (((cB ^ (rB & 7))) << 4);     \
            asm volatile("ldmatrix.sync.aligned.m8n8.x2.shared.b16 "         \
                         "{%0,%1}, [%2];"                                    \
                         : "=r"(bf[s][_nt][0]), "=r"(bf[s][_nt][1])          \
                         : "r"(addr));                                       \
        }                                                                    \
    } while (0)

    ISSUE_CHUNK(0);

    #pragma unroll 1
    for (int c = 0; c < NCHUNK; c++) {
        if (c < NCHUNK - 1) {
            ISSUE_CHUNK(c + 1);
            asm volatile("cp.async.wait_group 1;");
        } else {
            asm volatile("cp.async.wait_group 0;");
        }
        __syncthreads();

        const unsigned aBase = sb + (c & 1) * STAGE_BYTES;
        const unsigned bBase = aBase + 8192u;

        unsigned af[2][4][4], bf[2][4][2];
        LOAD_FRAGS(0, 0);

        #pragma unroll
        for (int ks = 0; ks < 4; ks++) {
            const int cur = ks & 1, nxt = cur ^ 1;
            if (ks < 3) LOAD_FRAGS(ks + 1, nxt);
            #pragma unroll
            for (int mt = 0; mt < 4; mt++)
                #pragma unroll
                for (int nt = 0; nt < 4; nt++)
                    asm volatile(
                        "mma.sync.aligned.m16n8k16.row.col.f16.f16.f16.f16 "
                        "{%0,%1}, {%2,%3,%4,%5}, {%6,%7}, {%0,%1};"
                        : "+r"(acc[mt][nt][0]), "+r"(acc[mt][nt][1])
                        : "r"(af[cur][mt][0]), "r"(af[cur][mt][1]),
                          "r"(af[cur][mt][2]), "r"(af[cur][mt][3]),
                          "r"(bf[cur][nt][0]), "r"(bf[cur][nt][1]));
        }
        __syncthreads();
    }

    // ---- epilogue: CTA-wide top-2 per (row, 128-col tile) ------------------
    s_top[tid] = 0ULL;                 // 128 entries = 64 rows x 2 slots
    __syncthreads();

    const int gq = lane >> 2;          // row group 0..7
    const int qt = lane & 3;           // col quad 0..3
    float esqv[4][2];
    #pragma unroll
    for (int nt = 0; nt < 4; nt++) {
        int cl = wn * 32 + nt * 8 + qt * 2;
        esqv[nt][0] = s_esq[cl];
        esqv[nt][1] = s_esq[cl + 1];
    }

    #pragma unroll
    for (int mt = 0; mt < 4; mt++) {
        int rl0 = mt * 16 + gq;        // local rows 0..63
        int rl1 = rl0 + 8;
        unsigned long long a0 = 0, b0 = 0, a1 = 0, b1 = 0;
        #pragma unroll
        for (int nt = 0; nt < 4; nt++) {
            int cg = colBase + wn * 32 + nt * 8 + qt * 2;
            float2 c01 = __half22float2(*(__half2*)&acc[mt][nt][0]);
            float2 c23 = __half22float2(*(__half2*)&acc[mt][nt][1]);
            merge2(a0, b0, pack_score(2.f * c01.x - esqv[nt][0], cg));
            merge2(a0, b0, pack_score(2.f * c01.y - esqv[nt][1], cg + 1));
            merge2(a1, b1, pack_score(2.f * c23.x - esqv[nt][0], cg));
            merge2(a1, b1, pack_score(2.f * c23.y - esqv[nt][1], cg + 1));
        }
        #pragma unroll
        for (int off = 1; off <= 2; off <<= 1) {
            unsigned long long xa0 = __shfl_xor_sync(0xffffffffu, a0, off);
            unsigned long long xb0 = __shfl_xor_sync(0xffffffffu, b0, off);
            unsigned long long xa1 = __shfl_xor_sync(0xffffffffu, a1, off);
            unsigned long long xb1 = __shfl_xor_sync(0xffffffffu, b1, off);
            merge2(a0, b0, xa0); merge2(a0, b0, xb0);
            merge2(a1, b1, xa1); merge2(a1, b1, xb1);
        }
        if (qt == 0) {
            // two-slot displacement merge: slot1 >= everything except the max
            unsigned long long old0 = atomicMax(&s_top[rl0 * 2], a0);
            unsigned long long l0 = min(old0, a0);
            atomicMax(&s_top[rl0 * 2 + 1], max(l0, b0));
            unsigned long long old1 = atomicMax(&s_top[rl1 * 2], a1);
            unsigned long long l1 = min(old1, a1);
            atomicMax(&s_top[rl1 * 2 + 1], max(l1, b1));
        }
    }
    __syncthreads();

    // flush: 2 slots per row -> g_cand[row][ctile*2 + s]
    g_cand[(size_t)(rowBase + (tid >> 1)) * CPR + blockIdx.x * 2 + (tid & 1)] =
        s_top[tid];
}

// ---------------- kernel 3: warp-per-row exact fp32 rescore + gather -------
__global__ __launch_bounds__(256)
void vq_rescore(const float* __restrict__ x, const float* __restrict__ embed,
                float* __restrict__ out, int write_idx) {
    const int warp = threadIdx.x >> 5, lane = threadIdx.x & 31;
    const int row = blockIdx.x * 8 + warp;
    __shared__ int s_idx[8][MAXCAND];
    __shared__ int s_cnt[8];
    if (lane == 0) s_cnt[warp] = 0;
    __syncwarp();

    const unsigned long long* cd = g_cand + (size_t)row * CPR;
    unsigned long long q[4];
    unsigned long long m = 0;
    #pragma unroll
    for (int i = 0; i < 4; i++) {
        q[i] = cd[i * 32 + lane];
        m = max(m, q[i]);
    }
    #pragma unroll
    for (int o = 16; o > 0; o >>= 1)
        m = max(m, __shfl_xor_sync(0xffffffffu, m, o));
    const float thr = unpack_score(m) - EPSF;

    #pragma unroll
    for (int i = 0; i < 4; i++) {
        if (unpack_score(q[i]) >= thr) {
            int k = atomicAdd(&s_cnt[warp], 1);
            if (k < MAXCAND) s_idx[warp][k] = unpack_idx(q[i]);
        }
    }
    __syncwarp();
    const int cnt = min(s_cnt[warp], MAXCAND);

    float4 xv[4];
    #pragma unroll
    for (int j = 0; j < 4; j++)
        xv[j] = ((const float4*)(x + (size_t)row * DIMV))[j * 32 + lane];

    unsigned long long best = 0ULL;
    for (int c = 0; c < cnt; c++) {
        const int idx = s_idx[warp][c];
        const float4* ev = (const float4*)(embed + (size_t)idx * DIMV);
        float d = 0.f;
        #pragma unroll
        for (int j = 0; j < 4; j++) {
            float4 e = ev[j * 32 + lane];
            d += xv[j].x * e.x + xv[j].y * e.y + xv[j].z * e.z + xv[j].w * e.w;
        }
        #pragma unroll
        for (int o = 16; o > 0; o >>= 1)
            d += __shfl_xor_sync(0xffffffffu, d, o);
        unsigned long long p = pack_score(2.0f * d - g_esq[idx], idx);
        if (p > best) best = p;
    }

    const int widx = unpack_idx(best);
    const float4* ev = (const float4*)(embed + (size_t)widx * DIMV);
    float4* dst = (float4*)(out + (size_t)row * DIMV);
    #pragma unroll
    for (int j = 0; j < 4; j++)
        dst[j * 32 + lane] = ev[j * 32 + lane];
    if (write_idx && lane == 0)
        out[(size_t)NROWS * DIMV + row] = (float)widx;
}

// ---------------- launch ----------------------------------------------------
extern "C" void kernel_launch(void* const* d_in, const int* in_sizes, int n_in,
                              void* d_out, int out_size) {
    const float* x     = (const float*)d_in[0];
    const float* embed = (const float*)d_in[1];
    float* out = (float*)d_out;

    cudaFuncSetAttribute(vq_gemm, cudaFuncAttributeMaxDynamicSharedMemorySize,
                         2 * STAGE_BYTES);

    vq_prep<<<NROWS, 128>>>(x, embed);

    dim3 grid(NCT, NROWS / BM);   // 64 x 256
    vq_gemm<<<grid, 128, 2 * STAGE_BYTES>>>();

    int write_idx = (out_size >= NROWS * DIMV + NROWS) ? 1 : 0;
    vq_rescore<<<NROWS / 8, 256>>>(x, embed, out, write_idx);
}